// round 3
// baseline (speedup 1.0000x reference)
#include <cuda_runtime.h>

#define N_NODES 100000
#define N_EDGES 1600000
#define IN_DIM 64
#define HID_DIM 128
#define OUT_DIM 40
#define NPG 8                       // nodes per group in fused MLP
#define NGROUPS (N_NODES / NPG)     // 12500 exact

// ---------------- scratch (static device arrays; no allocs) ----------------
__device__ __align__(16) float g_agg1[N_NODES * IN_DIM];   // x + S x
__device__ __align__(16) float g_t[N_NODES * OUT_DIM];     // h @ W3
__device__ __align__(16) float g_u[N_NODES * OUT_DIM];     // t + S t
__device__ int g_idx[2 * N_EDGES];                         // decoded src|dst
__device__ int g_is64;                                     // dtype flag

// ---------------- helpers ----------------
__device__ __forceinline__ void red_add4(float* p, float4 v) {
    asm volatile("red.global.add.v4.f32 [%0], {%1,%2,%3,%4};"
                 :: "l"(p), "f"(v.x), "f"(v.y), "f"(v.z), "f"(v.w)
                 : "memory");
}

// ---------------- K-detect: is edge_index int64 or int32? -------------------
// If the buffer really holds int64 indices, every 8-byte word is in
// [0, N_NODES). If it holds packed int32 pairs, the high 32 bits of most
// words are a second random index (nonzero), so the int64 view blows the
// range almost immediately.
__global__ void k_detect(const void* __restrict__ ei) {
    if (threadIdx.x != 0 || blockIdx.x != 0) return;
    const long long* p = (const long long*)ei;
    int ok64 = 1;
    for (int i = 0; i < 1024; i++) {
        long long v = p[i];
        if (v < 0 || v >= N_NODES) { ok64 = 0; break; }
    }
    g_is64 = ok64;
}

// ---------------- K-decode: g_idx[i] = edge_index[i] as int -----------------
__global__ void k_decode(const void* __restrict__ ei) {
    int i = blockIdx.x * blockDim.x + threadIdx.x;
    if (i >= 2 * N_EDGES) return;
    if (g_is64) g_idx[i] = (int)((const long long*)ei)[i];
    else        g_idx[i] = ((const int*)ei)[i];
}

// ---------------- K0: agg1 = x ----------------
__global__ void k_init(const float* __restrict__ x) {
    int i = blockIdx.x * blockDim.x + threadIdx.x;
    if (i < N_NODES * IN_DIM / 4) {
        reinterpret_cast<float4*>(g_agg1)[i] =
            reinterpret_cast<const float4*>(x)[i];
    }
}

// ---------------- K1: agg1[dst] += x[src]  (16 float4 per edge) -------------
__global__ void k_scatter1(const float* __restrict__ x) {
    int tid = blockIdx.x * blockDim.x + threadIdx.x;
    int e = tid >> 4;
    if (e >= N_EDGES) return;
    int c = tid & 15;
    int s = g_idx[e];
    int d = g_idx[N_EDGES + e];
    float4 v = *reinterpret_cast<const float4*>(x + (size_t)s * IN_DIM + c * 4);
    red_add4(g_agg1 + (size_t)d * IN_DIM + c * 4, v);
}

// ---------------- K2: fused MLP: t = relu(relu(agg1@W1+b1)@W2+b2) @ W3 ------
// also writes u = t (scatter2 accumulates on top of u)
constexpr int S_W1 = 0;                        // 64*128   = 8192 floats
constexpr int S_W2 = S_W1 + IN_DIM * HID_DIM;  // 128*128  = 16384
constexpr int S_W3 = S_W2 + HID_DIM * HID_DIM; // 128*40   = 5120
constexpr int S_B1 = S_W3 + HID_DIM * OUT_DIM;
constexpr int S_B2 = S_B1 + HID_DIM;
constexpr int S_A  = S_B2 + HID_DIM;           // [64][8]   transposed agg tile
constexpr int S_T  = S_A + IN_DIM * NPG;       // [128][8]  layer-1 activations
constexpr int S_H  = S_T + HID_DIM * NPG;      // [128][8]  layer-2 activations
constexpr int S_TOTAL = S_H + HID_DIM * NPG;
constexpr int SMEM_BYTES = S_TOTAL * 4;        // ~130 KB

__global__ void __launch_bounds__(256, 1)
k_mlp(const float* __restrict__ W1, const float* __restrict__ b1,
      const float* __restrict__ W2, const float* __restrict__ b2,
      const float* __restrict__ W3) {
    extern __shared__ float sm[];
    int tid = threadIdx.x;

    for (int i = tid; i < IN_DIM * HID_DIM; i += 256)  sm[S_W1 + i] = W1[i];
    for (int i = tid; i < HID_DIM * HID_DIM; i += 256) sm[S_W2 + i] = W2[i];
    for (int i = tid; i < HID_DIM * OUT_DIM; i += 256) sm[S_W3 + i] = W3[i];
    if (tid < HID_DIM) { sm[S_B1 + tid] = b1[tid]; sm[S_B2 + tid] = b2[tid]; }
    __syncthreads();

    int c   = tid & 127;   // output feature column
    int sub = tid >> 7;    // 0..1 -> which 4-node half of the group
    int nb  = sub * 4;

    for (int g = blockIdx.x; g < NGROUPS; g += gridDim.x) {
        int base = g * NPG;

        // stage agg1 tile, transposed to [k][node] so activations load as float4
        for (int i = tid; i < IN_DIM * NPG; i += 256) {
            int k = i & (IN_DIM - 1);
            int n = i >> 6;
            sm[S_A + k * NPG + n] = g_agg1[(size_t)(base + n) * IN_DIM + k];
        }
        __syncthreads();

        // ---- layer 1: 64 -> 128, relu ----
        float acc0, acc1, acc2, acc3;
        acc0 = acc1 = acc2 = acc3 = sm[S_B1 + c];
        #pragma unroll 8
        for (int k = 0; k < IN_DIM; k++) {
            float w  = sm[S_W1 + k * HID_DIM + c];
            float4 a = *reinterpret_cast<const float4*>(&sm[S_A + k * NPG + nb]);
            acc0 += w * a.x; acc1 += w * a.y; acc2 += w * a.z; acc3 += w * a.w;
        }
        float4 tv = make_float4(fmaxf(acc0, 0.f), fmaxf(acc1, 0.f),
                                fmaxf(acc2, 0.f), fmaxf(acc3, 0.f));
        *reinterpret_cast<float4*>(&sm[S_T + c * NPG + nb]) = tv;
        __syncthreads();

        // ---- layer 2: 128 -> 128, relu ----
        acc0 = acc1 = acc2 = acc3 = sm[S_B2 + c];
        #pragma unroll 8
        for (int k = 0; k < HID_DIM; k++) {
            float w  = sm[S_W2 + k * HID_DIM + c];
            float4 a = *reinterpret_cast<const float4*>(&sm[S_T + k * NPG + nb]);
            acc0 += w * a.x; acc1 += w * a.y; acc2 += w * a.z; acc3 += w * a.w;
        }
        float4 hv = make_float4(fmaxf(acc0, 0.f), fmaxf(acc1, 0.f),
                                fmaxf(acc2, 0.f), fmaxf(acc3, 0.f));
        *reinterpret_cast<float4*>(&sm[S_H + c * NPG + nb]) = hv;
        __syncthreads();

        // ---- projection: t = h @ W3 (128 -> 40); write t and u=t ----
        if (c < OUT_DIM) {
            acc0 = acc1 = acc2 = acc3 = 0.f;
            #pragma unroll 8
            for (int k = 0; k < HID_DIM; k++) {
                float w  = sm[S_W3 + k * OUT_DIM + c];
                float4 a = *reinterpret_cast<const float4*>(&sm[S_H + k * NPG + nb]);
                acc0 += w * a.x; acc1 += w * a.y; acc2 += w * a.z; acc3 += w * a.w;
            }
            size_t off = (size_t)(base + nb) * OUT_DIM + c;
            float* tp = g_t + off;
            float* up = g_u + off;
            tp[0 * OUT_DIM] = acc0; tp[1 * OUT_DIM] = acc1;
            tp[2 * OUT_DIM] = acc2; tp[3 * OUT_DIM] = acc3;
            up[0 * OUT_DIM] = acc0; up[1 * OUT_DIM] = acc1;
            up[2 * OUT_DIM] = acc2; up[3 * OUT_DIM] = acc3;
        }
        __syncthreads();
    }
}

// ---------------- K3: u[dst] += t[src]  (10 float4 per edge) ----------------
__global__ void k_scatter2() {
    long long tid = (long long)blockIdx.x * blockDim.x + threadIdx.x;
    if (tid >= (long long)N_EDGES * 10) return;
    int e = (int)(tid / 10);
    int c = (int)(tid - (long long)e * 10);
    int s = g_idx[e];
    int d = g_idx[N_EDGES + e];
    float4 v = *reinterpret_cast<const float4*>(g_t + (size_t)s * OUT_DIM + c * 4);
    red_add4(g_u + (size_t)d * OUT_DIM + c * 4, v);
}

// ---------------- K4: out = log_softmax(relu(u + b3)) -----------------------
__global__ void k_final(const float* __restrict__ b3, float* __restrict__ out) {
    int node = blockIdx.x * 8 + (threadIdx.x >> 5);
    if (node >= N_NODES) return;
    int l = threadIdx.x & 31;
    const float* u = g_u + (size_t)node * OUT_DIM;

    float a0 = fmaxf(u[l] + __ldg(&b3[l]), 0.f);
    bool has2 = l < (OUT_DIM - 32);
    float a1 = has2 ? fmaxf(u[32 + l] + __ldg(&b3[32 + l]), 0.f) : -3.4e38f;

    float m = fmaxf(a0, a1);
    #pragma unroll
    for (int o = 16; o > 0; o >>= 1) m = fmaxf(m, __shfl_xor_sync(0xffffffffu, m, o));

    float s = expf(a0 - m) + (has2 ? expf(a1 - m) : 0.f);
    #pragma unroll
    for (int o = 16; o > 0; o >>= 1) s += __shfl_xor_sync(0xffffffffu, s, o);

    float lse = m + logf(s);
    out[(size_t)node * OUT_DIM + l] = a0 - lse;
    if (has2) out[(size_t)node * OUT_DIM + 32 + l] = a1 - lse;
}

// ---------------- launch ----------------
extern "C" void kernel_launch(void* const* d_in, const int* in_sizes, int n_in,
                              void* d_out, int out_size) {
    const float* x  = (const float*)d_in[0];
    const void*  ei = d_in[1];
    const float* W1 = (const float*)d_in[2];
    const float* b1 = (const float*)d_in[3];
    const float* W2 = (const float*)d_in[4];
    const float* b2 = (const float*)d_in[5];
    const float* W3 = (const float*)d_in[6];
    const float* b3 = (const float*)d_in[7];
    float* out = (float*)d_out;

    static bool attr_set = false;
    if (!attr_set) {
        cudaFuncSetAttribute(k_mlp, cudaFuncAttributeMaxDynamicSharedMemorySize,
                             SMEM_BYTES);
        attr_set = true;
    }

    k_detect<<<1, 32>>>(ei);
    k_decode<<<(2 * N_EDGES + 255) / 256, 256>>>(ei);
    k_init<<<(N_NODES * IN_DIM / 4 + 255) / 256, 256>>>(x);
    k_scatter1<<<(N_EDGES * 16 + 255) / 256, 256>>>(x);
    k_mlp<<<148, 256, SMEM_BYTES>>>(W1, b1, W2, b2, W3);
    k_scatter2<<<(int)(((long long)N_EDGES * 10 + 255) / 256), 256>>>();
    k_final<<<(N_NODES + 7) / 8, 256>>>(b3, out);
}